// round 2
// baseline (speedup 1.0000x reference)
#include <cuda_runtime.h>
#include <math.h>

#define EMBED 768
#define HEADS 12
#define HDIM  64
#define BATCH 2
#define SEQ   2048
#define MROWS (BATCH * SEQ)      // 4096
#define BH    (BATCH * HEADS)    // 24
#define NX (MROWS * EMBED)       // 3145728
#define NW (EMBED * EMBED)       // 589824

// ---------------- scratch (no allocation allowed) ----------------
__device__ float g_Q[BH * SEQ * HDIM];     // [bh][s][d], pre-scaled by 1/sqrt(d)
__device__ float g_K[BH * SEQ * HDIM];
__device__ float g_V[BH * SEQ * HDIM];
__device__ float g_A[MROWS * EMBED];       // attention output, [b*S+s][e]

// ---------------- GEMM: Y = X @ W^T + b ----------------
// X: [4096, 768] row-major, W: [768, 768] row-major (W[n][k]), bias [768]
// mode 0: write to [bh][s][d] layout with scale applied after bias
// mode 1: write row-major [m][n]
#define BM 128
#define BN 64
#define BK 16

__global__ void __launch_bounds__(256)
gemm_bias_kernel(const float* __restrict__ X, const float* __restrict__ W,
                 const float* __restrict__ bias, float* __restrict__ Y,
                 int mode, float scale)
{
    __shared__ float Xs[BK][BM];   // [k][m]
    __shared__ float Ws[BK][BN];   // [k][n]

    const int tid = threadIdx.x;
    const int tx  = tid & 15;      // col group: n = tx*4
    const int ty  = tid >> 4;      // row group: m = ty*8
    const int m0  = blockIdx.y * BM;
    const int n0  = blockIdx.x * BN;

    const int xlrow = tid >> 1;          // 0..127
    const int xlcol = (tid & 1) * 8;     // 0 or 8
    const int wlrow = tid >> 2;          // 0..63
    const int wlcol = (tid & 3) * 4;     // 0,4,8,12

    float acc[8][4];
#pragma unroll
    for (int i = 0; i < 8; i++)
#pragma unroll
        for (int j = 0; j < 4; j++) acc[i][j] = 0.f;

    for (int k0 = 0; k0 < EMBED; k0 += BK) {
        float4 x0 = *(const float4*)&X[(size_t)(m0 + xlrow) * EMBED + k0 + xlcol];
        float4 x1 = *(const float4*)&X[(size_t)(m0 + xlrow) * EMBED + k0 + xlcol + 4];
        float4 wv = *(const float4*)&W[(size_t)(n0 + wlrow) * EMBED + k0 + wlcol];
        __syncthreads();
        Xs[xlcol + 0][xlrow] = x0.x;
        Xs[xlcol + 1][xlrow] = x0.y;
        Xs[xlcol + 2][xlrow] = x0.z;
        Xs[xlcol + 3][xlrow] = x0.w;
        Xs[xlcol + 4][xlrow] = x1.x;
        Xs[xlcol + 5][xlrow] = x1.y;
        Xs[xlcol + 6][xlrow] = x1.z;
        Xs[xlcol + 7][xlrow] = x1.w;
        Ws[wlcol + 0][wlrow] = wv.x;
        Ws[wlcol + 1][wlrow] = wv.y;
        Ws[wlcol + 2][wlrow] = wv.z;
        Ws[wlcol + 3][wlrow] = wv.w;
        __syncthreads();
#pragma unroll
        for (int kk = 0; kk < BK; kk++) {
            float4 a0 = *(const float4*)&Xs[kk][ty * 8];
            float4 a1 = *(const float4*)&Xs[kk][ty * 8 + 4];
            float4 b  = *(const float4*)&Ws[kk][tx * 4];
            float a[8] = {a0.x, a0.y, a0.z, a0.w, a1.x, a1.y, a1.z, a1.w};
            float bb[4] = {b.x, b.y, b.z, b.w};
#pragma unroll
            for (int i = 0; i < 8; i++)
#pragma unroll
                for (int j = 0; j < 4; j++)
                    acc[i][j] += a[i] * bb[j];
        }
    }

    const int nb = n0 + tx * 4;
    float4 bv = *(const float4*)&bias[nb];

    if (mode == 0) {
        const int h  = nb >> 6;
        const int d0 = nb & 63;
#pragma unroll
        for (int i = 0; i < 8; i++) {
            int m = m0 + ty * 8 + i;
            int b = m >> 11;          // / SEQ
            int s = m & 2047;
            float4 r;
            r.x = (acc[i][0] + bv.x) * scale;
            r.y = (acc[i][1] + bv.y) * scale;
            r.z = (acc[i][2] + bv.z) * scale;
            r.w = (acc[i][3] + bv.w) * scale;
            *(float4*)&Y[((size_t)(b * HEADS + h) * SEQ + s) * HDIM + d0] = r;
        }
    } else {
#pragma unroll
        for (int i = 0; i < 8; i++) {
            int m = m0 + ty * 8 + i;
            float4 r;
            r.x = acc[i][0] + bv.x;
            r.y = acc[i][1] + bv.y;
            r.z = acc[i][2] + bv.z;
            r.w = acc[i][3] + bv.w;
            *(float4*)&Y[(size_t)m * EMBED + nb] = r;
        }
    }
}

// ---------------- Flash attention (fp32, online softmax) ----------------
// Q,K,V: [bh][2048][64]; Q pre-scaled. Output -> g_A[(b*S+s)*768 + h*64 + d]
__global__ void __launch_bounds__(256)
flash_attn_kernel(const float* __restrict__ Q, const float* __restrict__ K,
                  const float* __restrict__ V, float* __restrict__ Aout)
{
    extern __shared__ float sm[];
    float* Qs = sm;            // [d][r]  64x64
    float* Ks = sm + 4096;     // [d][c]  64x64
    float* Vs = sm + 8192;     // [k][d]  64x64
    float* Ps = sm + 12288;    // [r][k]  64x64

    const int tid = threadIdx.x;
    const int tx  = tid & 15;
    const int ty  = tid >> 4;
    const int bh  = blockIdx.y;
    const int q0  = blockIdx.x * 64;

    const float* Qb = Q + (size_t)bh * SEQ * HDIM;
    const float* Kb = K + (size_t)bh * SEQ * HDIM;
    const float* Vb = V + (size_t)bh * SEQ * HDIM;

    const int lrow = tid >> 2;        // 0..63
    const int lc0  = (tid & 3) * 4;   // 0,4,8,12

    // load full 64x64 Q tile transposed: Qs[d][r]  (4 float4 per thread)
#pragma unroll
    for (int j = 0; j < 4; j++) {
        int c = lc0 + j * 16;
        float4 qv = *(const float4*)&Qb[(size_t)(q0 + lrow) * HDIM + c];
        Qs[(c + 0) * 64 + lrow] = qv.x;
        Qs[(c + 1) * 64 + lrow] = qv.y;
        Qs[(c + 2) * 64 + lrow] = qv.z;
        Qs[(c + 3) * 64 + lrow] = qv.w;
    }

    float m_run[4], l_run[4], o[4][4];
#pragma unroll
    for (int i = 0; i < 4; i++) {
        m_run[i] = -INFINITY;
        l_run[i] = 0.f;
#pragma unroll
        for (int j = 0; j < 4; j++) o[i][j] = 0.f;
    }
    __syncthreads();

    for (int kt = 0; kt < SEQ / 64; kt++) {
        const int k0 = kt * 64;
        float4 kv[4], vv[4];
#pragma unroll
        for (int j = 0; j < 4; j++) {
            int c = lc0 + j * 16;
            kv[j] = *(const float4*)&Kb[(size_t)(k0 + lrow) * HDIM + c];
            vv[j] = *(const float4*)&Vb[(size_t)(k0 + lrow) * HDIM + c];
        }
        __syncthreads();   // previous tile fully consumed
#pragma unroll
        for (int j = 0; j < 4; j++) {
            int c = lc0 + j * 16;
            Ks[(c + 0) * 64 + lrow] = kv[j].x;
            Ks[(c + 1) * 64 + lrow] = kv[j].y;
            Ks[(c + 2) * 64 + lrow] = kv[j].z;
            Ks[(c + 3) * 64 + lrow] = kv[j].w;
            *(float4*)&Vs[lrow * 64 + c] = vv[j];
        }
        __syncthreads();

        // S = Q K^T  (64x64x64)
        float sacc[4][4];
#pragma unroll
        for (int i = 0; i < 4; i++)
#pragma unroll
            for (int j = 0; j < 4; j++) sacc[i][j] = 0.f;

#pragma unroll
        for (int d = 0; d < HDIM; d++) {
            float4 a = *(const float4*)&Qs[d * 64 + ty * 4];
            float4 b = *(const float4*)&Ks[d * 64 + tx * 4];
            sacc[0][0] += a.x * b.x; sacc[0][1] += a.x * b.y; sacc[0][2] += a.x * b.z; sacc[0][3] += a.x * b.w;
            sacc[1][0] += a.y * b.x; sacc[1][1] += a.y * b.y; sacc[1][2] += a.y * b.z; sacc[1][3] += a.y * b.w;
            sacc[2][0] += a.z * b.x; sacc[2][1] += a.z * b.y; sacc[2][2] += a.z * b.z; sacc[2][3] += a.z * b.w;
            sacc[3][0] += a.w * b.x; sacc[3][1] += a.w * b.y; sacc[3][2] += a.w * b.z; sacc[3][3] += a.w * b.w;
        }

        // online softmax per row (row group = 16 lanes, same half-warp)
#pragma unroll
        for (int i = 0; i < 4; i++) {
            float pm = fmaxf(fmaxf(sacc[i][0], sacc[i][1]), fmaxf(sacc[i][2], sacc[i][3]));
#pragma unroll
            for (int off = 8; off >= 1; off >>= 1)
                pm = fmaxf(pm, __shfl_xor_sync(0xffffffffu, pm, off, 16));
            float mn = fmaxf(m_run[i], pm);
            float alpha = __expf(m_run[i] - mn);
            float ps = 0.f;
#pragma unroll
            for (int j = 0; j < 4; j++) {
                float p = __expf(sacc[i][j] - mn);
                sacc[i][j] = p;
                ps += p;
            }
#pragma unroll
            for (int off = 8; off >= 1; off >>= 1)
                ps += __shfl_xor_sync(0xffffffffu, ps, off, 16);
            l_run[i] = l_run[i] * alpha + ps;
            m_run[i] = mn;
#pragma unroll
            for (int j = 0; j < 4; j++) o[i][j] *= alpha;
            float4 pr = make_float4(sacc[i][0], sacc[i][1], sacc[i][2], sacc[i][3]);
            *(float4*)&Ps[(ty * 4 + i) * 64 + tx * 4] = pr;
        }
        __syncthreads();

        // O += P V   (64x64x64)
#pragma unroll
        for (int k = 0; k < 64; k += 4) {
            float4 v0 = *(const float4*)&Vs[(k + 0) * 64 + tx * 4];
            float4 v1 = *(const float4*)&Vs[(k + 1) * 64 + tx * 4];
            float4 v2 = *(const float4*)&Vs[(k + 2) * 64 + tx * 4];
            float4 v3 = *(const float4*)&Vs[(k + 3) * 64 + tx * 4];
#pragma unroll
            for (int i = 0; i < 4; i++) {
                float4 p = *(const float4*)&Ps[(ty * 4 + i) * 64 + k];
                o[i][0] += p.x * v0.x + p.y * v1.x + p.z * v2.x + p.w * v3.x;
                o[i][1] += p.x * v0.y + p.y * v1.y + p.z * v2.y + p.w * v3.y;
                o[i][2] += p.x * v0.z + p.y * v1.z + p.z * v2.z + p.w * v3.z;
                o[i][3] += p.x * v0.w + p.y * v1.w + p.z * v2.w + p.w * v3.w;
            }
        }
    }

    // finalize and scatter to [b][s][e] with e = h*64 + d
    const int b = bh / HEADS;
    const int h = bh % HEADS;
#pragma unroll
    for (int i = 0; i < 4; i++) {
        int s = q0 + ty * 4 + i;
        float inv = 1.f / l_run[i];
        float4 r;
        r.x = o[i][0] * inv;
        r.y = o[i][1] * inv;
        r.z = o[i][2] * inv;
        r.w = o[i][3] * inv;
        *(float4*)&Aout[((size_t)(b * SEQ + s)) * EMBED + h * HDIM + tx * 4] = r;
    }
}

// ---------------- driver ----------------
extern "C" void kernel_launch(void* const* d_in, const int* in_sizes, int n_in,
                              void* d_out, int out_size)
{
    // Default: signature order (x, w_q, b_q, w_k, b_k, w_v, b_v, w_o, b_o)
    const float *x, *w_q, *b_q, *w_k, *b_k, *w_v, *b_v, *w_o, *b_o;
    if (n_in == 9 && in_sizes[0] == EMBED && in_sizes[8] == NX) {
        // alphabetical: b_k, b_o, b_q, b_v, w_k, w_o, w_q, w_v, x
        b_k = (const float*)d_in[0];
        b_o = (const float*)d_in[1];
        b_q = (const float*)d_in[2];
        b_v = (const float*)d_in[3];
        w_k = (const float*)d_in[4];
        w_o = (const float*)d_in[5];
        w_q = (const float*)d_in[6];
        w_v = (const float*)d_in[7];
        x   = (const float*)d_in[8];
    } else if (n_in == 9 && in_sizes[0] == NX && in_sizes[2] == NW) {
        // grouped: x, w_q, w_k, w_v, w_o, b_q, b_k, b_v, b_o
        x   = (const float*)d_in[0];
        w_q = (const float*)d_in[1];
        w_k = (const float*)d_in[2];
        w_v = (const float*)d_in[3];
        w_o = (const float*)d_in[4];
        b_q = (const float*)d_in[5];
        b_k = (const float*)d_in[6];
        b_v = (const float*)d_in[7];
        b_o = (const float*)d_in[8];
    } else {
        x   = (const float*)d_in[0];
        w_q = (const float*)d_in[1];
        b_q = (const float*)d_in[2];
        w_k = (const float*)d_in[3];
        b_k = (const float*)d_in[4];
        w_v = (const float*)d_in[5];
        b_v = (const float*)d_in[6];
        w_o = (const float*)d_in[7];
        b_o = (const float*)d_in[8];
    }
    float* out = (float*)d_out;

    float *gQ, *gK, *gV, *gA;
    cudaGetSymbolAddress((void**)&gQ, g_Q);
    cudaGetSymbolAddress((void**)&gK, g_K);
    cudaGetSymbolAddress((void**)&gV, g_V);
    cudaGetSymbolAddress((void**)&gA, g_A);

    cudaFuncSetAttribute(flash_attn_kernel,
                         cudaFuncAttributeMaxDynamicSharedMemorySize, 65536);

    dim3 ggrid(EMBED / BN, MROWS / BM);   // (12, 32)
    const float qscale = 0.125f;          // 1/sqrt(HDIM)

    gemm_bias_kernel<<<ggrid, 256>>>(x, w_q, b_q, gQ, 0, qscale);
    gemm_bias_kernel<<<ggrid, 256>>>(x, w_k, b_k, gK, 0, 1.0f);
    gemm_bias_kernel<<<ggrid, 256>>>(x, w_v, b_v, gV, 0, 1.0f);

    dim3 agrid(SEQ / 64, BH);             // (32, 24)
    flash_attn_kernel<<<agrid, 256, 65536>>>(gQ, gK, gV, gA);

    gemm_bias_kernel<<<ggrid, 256>>>(gA, w_o, b_o, out, 1, 1.0f);
}